// round 15
// baseline (speedup 1.0000x reference)
#include <cuda_runtime.h>
#include <cstdint>

// QuantumCircuitSimulator2: 24 qubits, 8 steps of 4-qubit (16x16 complex) gates.
// One gate per kernel; each thread processes TWO 16-amplitude groups (G=2) so
// every gate-table load (constant memory, uniform LDCU port) is amortized
// over two groups. Karatsuba complex matvec (A=gr, B=gr+gi, C=gi-gr) on
// fma.rn.f32x2. Interleaved float2 state in __device__ scratch between steps.

#define NQ 24
#define NSTATE (1u << NQ)
#define NGROUPS (1u << (NQ - 4))     // 2^20
#define NTHREADS_TOT (NGROUPS / 2)   // 2^19 threads, G=2
#define NSTEPS 8

typedef unsigned long long u64;

// interleaved scratch state (float2 per amplitude) — static device array
__device__ __align__(16) float QS_scratch[1u << 25];
// staging for Karatsuba tables before upload to constant
__device__ __align__(16) float QS_tables[NSTEPS * 768];

// Karatsuba tables: [step][3][16][16] floats = 24 KB
__constant__ __align__(16) float cGK[NSTEPS * 768];

__device__ __forceinline__ void fma2_acc(u64& acc, u64 a, u64 b) {
    asm("fma.rn.f32x2 %0, %1, %2, %0;" : "+l"(acc) : "l"(a), "l"(b));
}
__device__ __forceinline__ u64 mul2(u64 a, u64 b) {
    u64 d;
    asm("mul.rn.f32x2 %0, %1, %2;" : "=l"(d) : "l"(a), "l"(b));
    return d;
}
__device__ __forceinline__ u64 add2(u64 a, u64 b) {
    u64 d;
    asm("add.rn.f32x2 %0, %1, %2;" : "=l"(d) : "l"(a), "l"(b));
    return d;
}
__device__ __forceinline__ u64 pack2(float lo, float hi) {
    u64 d;
    asm("mov.b64 %0, {%1, %2};" : "=l"(d) : "f"(lo), "f"(hi));
    return d;
}
__device__ __forceinline__ void unpack2(u64 v, float& lo, float& hi) {
    asm("mov.b64 {%0, %1}, %2;" : "=f"(lo), "=f"(hi) : "l"(v));
}

// Build Karatsuba tables for all steps: A=gr, B=gr+gi, C=gi-gr.
__global__ void qprep_kernel(const float* __restrict__ gates) {
    int step = blockIdx.x;
    const float* g = gates + (size_t)step * 512;
    for (int i = threadIdx.x; i < 768; i += blockDim.x) {
        int t = i >> 8;
        int idx = i & 255;
        float gr = g[idx];
        float gi = g[256 + idx];
        QS_tables[step * 768 + i] =
            (t == 0) ? gr : ((t == 1) ? (gr + gi) : (gi - gr));
    }
}

// IN_PLANAR: src is [2, 2^24] planar re/im. Otherwise interleaved float2.
// OUT_PLANAR: dst is planar. Otherwise interleaved float2.
template <int IN_PLANAR, int OUT_PLANAR>
__global__ __launch_bounds__(256, 2)
void qgate_kernel(const float* __restrict__ src,
                  float* __restrict__ dst,
                  const int* __restrict__ targets_raw,
                  int step) {
    const int tid = threadIdx.x;

    // dtype detect: int64 targets (<24) have zero odd 32-bit words
    int stride = (targets_raw[1] == 0 && targets_raw[3] == 0) ? 2 : 1;
    int q0 = targets_raw[(step * 4 + 0) * stride];
    int q1 = targets_raw[(step * 4 + 1) * stride];
    int q2 = targets_raw[(step * 4 + 2) * stride];
    int q3 = targets_raw[(step * 4 + 3) * stride];
    unsigned m0 = 1u << q0, m1 = 1u << q1, m2 = 1u << q2, m3 = 1u << q3;

    // sorted copy for ascending zero-bit insertion
    int a = q0, b = q1, c = q2, d = q3, t;
    if (a > b) { t = a; a = b; b = t; }
    if (c > d) { t = c; c = d; d = t; }
    if (a > c) { t = a; a = c; c = t; }
    if (b > d) { t = b; b = d; d = t; }
    if (b > c) { t = b; b = c; c = t; }

    // two groups per thread: gid and gid + 2^19
    unsigned gid = blockIdx.x * 256u + tid;
    unsigned base0, base1;
    {
        unsigned g0 = gid;
        g0 = ((g0 >> a) << (a + 1)) | (g0 & ((1u << a) - 1u));
        g0 = ((g0 >> b) << (b + 1)) | (g0 & ((1u << b) - 1u));
        g0 = ((g0 >> c) << (c + 1)) | (g0 & ((1u << c) - 1u));
        g0 = ((g0 >> d) << (d + 1)) | (g0 & ((1u << d) - 1u));
        base0 = g0;
        unsigned g1 = gid + (unsigned)NTHREADS_TOT;
        g1 = ((g1 >> a) << (a + 1)) | (g1 & ((1u << a) - 1u));
        g1 = ((g1 >> b) << (b + 1)) | (g1 & ((1u << b) - 1u));
        g1 = ((g1 >> c) << (c + 1)) | (g1 & ((1u << c) - 1u));
        g1 = ((g1 >> d) << (d + 1)) | (g1 & ((1u << d) - 1u));
        base1 = g1;
    }

    // ---- gather 16 amplitudes per group, pack along k into f32x2 pairs ----
    u64 srA[8], siA[8], uA[8];
    u64 srB[8], siB[8], uB[8];
#pragma unroll
    for (int kk = 0; kk < 8; kk++) {
        unsigned off = ((kk & 1) ? m1 : 0u) + ((kk & 2) ? m2 : 0u) +
                       ((kk & 4) ? m3 : 0u);
        unsigned oA0 = base0 + off, oA1 = oA0 + m0;
        unsigned oB0 = base1 + off, oB1 = oB0 + m0;
        float rA0, iA0, rA1, iA1, rB0, iB0, rB1, iB1;
        if (IN_PLANAR) {
            rA0 = src[oA0]; iA0 = src[NSTATE + oA0];
            rA1 = src[oA1]; iA1 = src[NSTATE + oA1];
            rB0 = src[oB0]; iB0 = src[NSTATE + oB0];
            rB1 = src[oB1]; iB1 = src[NSTATE + oB1];
        } else {
            const float2* s2 = reinterpret_cast<const float2*>(src);
            float2 vA0 = s2[oA0], vA1 = s2[oA1];
            float2 vB0 = s2[oB0], vB1 = s2[oB1];
            rA0 = vA0.x; iA0 = vA0.y; rA1 = vA1.x; iA1 = vA1.y;
            rB0 = vB0.x; iB0 = vB0.y; rB1 = vB1.x; iB1 = vB1.y;
        }
        srA[kk] = pack2(rA0, rA1);
        siA[kk] = pack2(iA0, iA1);
        uA[kk]  = add2(srA[kk], siA[kk]);
        srB[kk] = pack2(rB0, rB1);
        siB[kk] = pack2(iB0, iB1);
        uB[kk]  = add2(srB[kk], siB[kk]);
    }

    const float* gbase = cGK + step * 768;
    const u64 NEG1 = pack2(-1.0f, -1.0f);
#pragma unroll
    for (int j = 0; j < 16; j++) {
        // One set of table-row loads (uniform LDCU) serves BOTH groups.
        const ulonglong2* A2 = reinterpret_cast<const ulonglong2*>(gbase + j * 16);
        const ulonglong2* B2 = reinterpret_cast<const ulonglong2*>(gbase + 256 + j * 16);
        const ulonglong2* C2 = reinterpret_cast<const ulonglong2*>(gbase + 512 + j * 16);
        ulonglong2 av = A2[0], bv = B2[0], cv = C2[0];
        u64 a1A = mul2(av.x, uA[0]);
        u64 a2A = mul2(bv.x, siA[0]);
        u64 a3A = mul2(cv.x, srA[0]);
        u64 a1B = mul2(av.x, uB[0]);
        u64 a2B = mul2(bv.x, siB[0]);
        u64 a3B = mul2(cv.x, srB[0]);
        fma2_acc(a1A, av.y, uA[1]);
        fma2_acc(a2A, bv.y, siA[1]);
        fma2_acc(a3A, cv.y, srA[1]);
        fma2_acc(a1B, av.y, uB[1]);
        fma2_acc(a2B, bv.y, siB[1]);
        fma2_acc(a3B, cv.y, srB[1]);
#pragma unroll
        for (int q = 1; q < 4; q++) {
            av = A2[q]; bv = B2[q]; cv = C2[q];
            fma2_acc(a1A, av.x, uA[2 * q]);
            fma2_acc(a2A, bv.x, siA[2 * q]);
            fma2_acc(a3A, cv.x, srA[2 * q]);
            fma2_acc(a1B, av.x, uB[2 * q]);
            fma2_acc(a2B, bv.x, siB[2 * q]);
            fma2_acc(a3B, cv.x, srB[2 * q]);
            fma2_acc(a1A, av.y, uA[2 * q + 1]);
            fma2_acc(a2A, bv.y, siA[2 * q + 1]);
            fma2_acc(a3A, cv.y, srA[2 * q + 1]);
            fma2_acc(a1B, av.y, uB[2 * q + 1]);
            fma2_acc(a2B, bv.y, siB[2 * q + 1]);
            fma2_acc(a3B, cv.y, srB[2 * q + 1]);
        }
        unsigned jo = ((j & 1) ? m0 : 0u) + ((j & 2) ? m1 : 0u) +
                      ((j & 4) ? m2 : 0u) + ((j & 8) ? m3 : 0u);
        {
            u64 dim = add2(a1A, a3A);
            fma2_acc(a1A, a2A, NEG1);
            float rl, rh, il, ih;
            unpack2(a1A, rl, rh);
            unpack2(dim, il, ih);
            float re = rl + rh, im = il + ih;
            unsigned oj = base0 + jo;
            if (OUT_PLANAR) {
                dst[oj] = re;
                dst[NSTATE + oj] = im;
            } else {
                reinterpret_cast<float2*>(dst)[oj] = make_float2(re, im);
            }
        }
        {
            u64 dim = add2(a1B, a3B);
            fma2_acc(a1B, a2B, NEG1);
            float rl, rh, il, ih;
            unpack2(a1B, rl, rh);
            unpack2(dim, il, ih);
            float re = rl + rh, im = il + ih;
            unsigned oj = base1 + jo;
            if (OUT_PLANAR) {
                dst[oj] = re;
                dst[NSTATE + oj] = im;
            } else {
                reinterpret_cast<float2*>(dst)[oj] = make_float2(re, im);
            }
        }
    }
}

extern "C" void kernel_launch(void* const* d_in, const int* in_sizes, int n_in,
                              void* d_out, int out_size) {
    const float* state   = (const float*)d_in[0];
    const int*   targets = (const int*)d_in[1];
    const float* gates   = (const float*)d_in[2];
    float*       out     = (float*)d_out;

    void* scratch_ptr = nullptr;
    cudaGetSymbolAddress(&scratch_ptr, QS_scratch);
    float* scratch = (float*)scratch_ptr;

    void* tables_ptr = nullptr;
    cudaGetSymbolAddress(&tables_ptr, QS_tables);

    // build Karatsuba tables, then upload to constant memory (DtoD, capture-safe)
    qprep_kernel<<<NSTEPS, 256>>>(gates);
    cudaMemcpyToSymbolAsync(cGK, tables_ptr, NSTEPS * 768 * sizeof(float), 0,
                            cudaMemcpyDeviceToDevice);

    dim3 block(256);
    dim3 grid(NTHREADS_TOT / 256);  // 2048 blocks, 2 groups per thread

    // step 0: planar input -> interleaved scratch
    qgate_kernel<1, 0><<<grid, block>>>(state, scratch, targets, 0);
    // steps 1..6: interleaved in-place (each thread owns its two groups)
    for (int s = 1; s < NSTEPS - 1; s++) {
        qgate_kernel<0, 0><<<grid, block>>>(scratch, scratch, targets, s);
    }
    // step 7: interleaved -> planar output
    qgate_kernel<0, 1><<<grid, block>>>(scratch, out, targets, NSTEPS - 1);
}

// round 16
// speedup vs baseline: 1.1031x; 1.1031x over previous
#include <cuda_runtime.h>
#include <cstdint>

// QuantumCircuitSimulator2: 24 qubits, 8 steps of 4-qubit (16x16 complex) gates.
// One gate per kernel, ONE 16-amplitude group per thread (G=1 — round-14
// winner), Karatsuba complex matvec (A=gr, B=gr+gi, C=gi-gr) on fma.rn.f32x2,
// gate tables in __constant__ (uniform LDCU port).
// This round: 128-thread blocks with __launch_bounds__(128, 7) -> 72-reg cap,
// 28 warps/SM (vs 24), buying issue-rate for the issue-bound stream.

#define NQ 24
#define NSTATE (1u << NQ)
#define NGROUPS (1u << (NQ - 4))     // 2^20
#define NSTEPS 8

typedef unsigned long long u64;

// interleaved scratch state (float2 per amplitude) — static device array
__device__ __align__(16) float QS_scratch[1u << 25];
// staging for Karatsuba tables before upload to constant
__device__ __align__(16) float QS_tables[NSTEPS * 768];

// Karatsuba tables: [step][3][16][16] floats = 24 KB
__constant__ __align__(16) float cGK[NSTEPS * 768];

__device__ __forceinline__ void fma2_acc(u64& acc, u64 a, u64 b) {
    asm("fma.rn.f32x2 %0, %1, %2, %0;" : "+l"(acc) : "l"(a), "l"(b));
}
__device__ __forceinline__ u64 mul2(u64 a, u64 b) {
    u64 d;
    asm("mul.rn.f32x2 %0, %1, %2;" : "=l"(d) : "l"(a), "l"(b));
    return d;
}
__device__ __forceinline__ u64 add2(u64 a, u64 b) {
    u64 d;
    asm("add.rn.f32x2 %0, %1, %2;" : "=l"(d) : "l"(a), "l"(b));
    return d;
}
__device__ __forceinline__ u64 pack2(float lo, float hi) {
    u64 d;
    asm("mov.b64 %0, {%1, %2};" : "=l"(d) : "f"(lo), "f"(hi));
    return d;
}
__device__ __forceinline__ void unpack2(u64 v, float& lo, float& hi) {
    asm("mov.b64 {%0, %1}, %2;" : "=f"(lo), "=f"(hi) : "l"(v));
}

// Build Karatsuba tables for all steps: A=gr, B=gr+gi, C=gi-gr.
__global__ void qprep_kernel(const float* __restrict__ gates) {
    int step = blockIdx.x;
    const float* g = gates + (size_t)step * 512;
    for (int i = threadIdx.x; i < 768; i += blockDim.x) {
        int t = i >> 8;
        int idx = i & 255;
        float gr = g[idx];
        float gi = g[256 + idx];
        QS_tables[step * 768 + i] =
            (t == 0) ? gr : ((t == 1) ? (gr + gi) : (gi - gr));
    }
}

// IN_PLANAR: src is [2, 2^24] planar re/im. Otherwise interleaved float2.
// OUT_PLANAR: dst is planar. Otherwise interleaved float2.
template <int IN_PLANAR, int OUT_PLANAR>
__global__ __launch_bounds__(128, 7)
void qgate_kernel(const float* __restrict__ src,
                  float* __restrict__ dst,
                  const int* __restrict__ targets_raw,
                  int step) {
    const int tid = threadIdx.x;

    // dtype detect: int64 targets (<24) have zero odd 32-bit words
    int stride = (targets_raw[1] == 0 && targets_raw[3] == 0) ? 2 : 1;
    int q0 = targets_raw[(step * 4 + 0) * stride];
    int q1 = targets_raw[(step * 4 + 1) * stride];
    int q2 = targets_raw[(step * 4 + 2) * stride];
    int q3 = targets_raw[(step * 4 + 3) * stride];
    unsigned m0 = 1u << q0, m1 = 1u << q1, m2 = 1u << q2, m3 = 1u << q3;

    // sorted copy for ascending zero-bit insertion
    int a = q0, b = q1, c = q2, d = q3, t;
    if (a > b) { t = a; a = b; b = t; }
    if (c > d) { t = c; c = d; d = t; }
    if (a > c) { t = a; a = c; c = t; }
    if (b > d) { t = b; b = d; d = t; }
    if (b > c) { t = b; b = c; c = t; }

    unsigned g20 = blockIdx.x * 128u + tid;
    unsigned base = g20;
    base = ((base >> a) << (a + 1)) | (base & ((1u << a) - 1u));
    base = ((base >> b) << (b + 1)) | (base & ((1u << b) - 1u));
    base = ((base >> c) << (c + 1)) | (base & ((1u << c) - 1u));
    base = ((base >> d) << (d + 1)) | (base & ((1u << d) - 1u));

    // ---- gather 16 amplitudes, pack along k into f32x2 pairs ----
    u64 sr2[8], si2[8], u2[8];
#pragma unroll
    for (int kk = 0; kk < 8; kk++) {
        unsigned o0 = base + ((kk & 1) ? m1 : 0u) +
                      ((kk & 2) ? m2 : 0u) + ((kk & 4) ? m3 : 0u);
        unsigned o1 = o0 + m0;
        float r0, i0, r1, i1;
        if (IN_PLANAR) {
            r0 = src[o0];
            i0 = src[NSTATE + o0];
            r1 = src[o1];
            i1 = src[NSTATE + o1];
        } else {
            const float2* s2 = reinterpret_cast<const float2*>(src);
            float2 v0 = s2[o0];
            float2 v1 = s2[o1];
            r0 = v0.x; i0 = v0.y;
            r1 = v1.x; i1 = v1.y;
        }
        sr2[kk] = pack2(r0, r1);
        si2[kk] = pack2(i0, i1);
        u2[kk]  = add2(sr2[kk], si2[kk]);   // sr + si
    }

    const float* gbase = cGK + step * 768;
    const u64 NEG1 = pack2(-1.0f, -1.0f);
#pragma unroll
    for (int j = 0; j < 16; j++) {
        // Table rows from __constant__ (uniform LDCU). Rows: A=gr, B=gr+gi,
        // C=gi-gr; .x/.y of each ulonglong2 ARE the packed f32x2 pairs.
        const ulonglong2* A2 = reinterpret_cast<const ulonglong2*>(gbase + j * 16);
        const ulonglong2* B2 = reinterpret_cast<const ulonglong2*>(gbase + 256 + j * 16);
        const ulonglong2* C2 = reinterpret_cast<const ulonglong2*>(gbase + 512 + j * 16);
        ulonglong2 av = A2[0], bv = B2[0], cv = C2[0];
        u64 a1 = mul2(av.x, u2[0]);    // gr*(sr+si)
        u64 a2 = mul2(bv.x, si2[0]);   // (gr+gi)*si
        u64 a3 = mul2(cv.x, sr2[0]);   // (gi-gr)*sr
        fma2_acc(a1, av.y, u2[1]);
        fma2_acc(a2, bv.y, si2[1]);
        fma2_acc(a3, cv.y, sr2[1]);
#pragma unroll
        for (int q = 1; q < 4; q++) {
            av = A2[q]; bv = B2[q]; cv = C2[q];
            fma2_acc(a1, av.x, u2[2 * q]);
            fma2_acc(a2, bv.x, si2[2 * q]);
            fma2_acc(a3, cv.x, sr2[2 * q]);
            fma2_acc(a1, av.y, u2[2 * q + 1]);
            fma2_acc(a2, bv.y, si2[2 * q + 1]);
            fma2_acc(a3, cv.y, sr2[2 * q + 1]);
        }
        u64 dim = add2(a1, a3);        // im pair = a1 + a3 (before a1 is consumed)
        fma2_acc(a1, a2, NEG1);        // re pair = a1 - a2
        float rl, rh, il, ih;
        unpack2(a1, rl, rh);
        unpack2(dim, il, ih);
        float re = rl + rh;
        float im = il + ih;
        unsigned oj = base + ((j & 1) ? m0 : 0u) + ((j & 2) ? m1 : 0u) +
                      ((j & 4) ? m2 : 0u) + ((j & 8) ? m3 : 0u);
        if (OUT_PLANAR) {
            dst[oj] = re;
            dst[NSTATE + oj] = im;
        } else {
            reinterpret_cast<float2*>(dst)[oj] = make_float2(re, im);
        }
    }
}

extern "C" void kernel_launch(void* const* d_in, const int* in_sizes, int n_in,
                              void* d_out, int out_size) {
    const float* state   = (const float*)d_in[0];
    const int*   targets = (const int*)d_in[1];
    const float* gates   = (const float*)d_in[2];
    float*       out     = (float*)d_out;

    void* scratch_ptr = nullptr;
    cudaGetSymbolAddress(&scratch_ptr, QS_scratch);
    float* scratch = (float*)scratch_ptr;

    void* tables_ptr = nullptr;
    cudaGetSymbolAddress(&tables_ptr, QS_tables);

    // build Karatsuba tables, then upload to constant memory (DtoD, capture-safe)
    qprep_kernel<<<NSTEPS, 256>>>(gates);
    cudaMemcpyToSymbolAsync(cGK, tables_ptr, NSTEPS * 768 * sizeof(float), 0,
                            cudaMemcpyDeviceToDevice);

    dim3 block(128);
    dim3 grid(NGROUPS / 128);  // 8192 blocks

    // step 0: planar input -> interleaved scratch
    qgate_kernel<1, 0><<<grid, block>>>(state, scratch, targets, 0);
    // steps 1..6: interleaved in-place (each thread owns its group)
    for (int s = 1; s < NSTEPS - 1; s++) {
        qgate_kernel<0, 0><<<grid, block>>>(scratch, scratch, targets, s);
    }
    // step 7: interleaved -> planar output
    qgate_kernel<0, 1><<<grid, block>>>(scratch, out, targets, NSTEPS - 1);
}